// round 3
// baseline (speedup 1.0000x reference)
#include <cuda_runtime.h>
#include <cuda_fp16.h>
#include <cstdint>

#define BB 64
#define TSTEPS 512
#define HH 512
#define NCTA 128

// ---------------- static device scratch (no allocations allowed) ----------------
__device__ __align__(16) __half g_xh[TSTEPS * BB * 256];        // x cast fp16, [T][B][256]
__device__ __align__(16) __half g_h0[(TSTEPS + 1) * BB * HH];   // layer0 h seq, slot0 = 0
__device__ __align__(16) __half g_h1[(TSTEPS + 1) * BB * HH];   // layer1 h seq, slot0 = 0
__device__ unsigned g_cnt = 0;
__device__ unsigned g_gen = 0;

// ---------------- PTX helpers ----------------
__device__ __forceinline__ void cp16(uint32_t dst, const void* src) {
    asm volatile("cp.async.cg.shared.global [%0], [%1], 16;\n" :: "r"(dst), "l"(src));
}
__device__ __forceinline__ void cp_commit() { asm volatile("cp.async.commit_group;\n"); }
template<int N> __device__ __forceinline__ void cp_wait() {
    asm volatile("cp.async.wait_group %0;\n" :: "n"(N));
}
__device__ __forceinline__ void ldsm4(uint32_t& r0, uint32_t& r1, uint32_t& r2, uint32_t& r3,
                                      uint32_t a) {
    asm volatile("ldmatrix.sync.aligned.m8n8.x4.shared.b16 {%0,%1,%2,%3}, [%4];\n"
                 : "=r"(r0), "=r"(r1), "=r"(r2), "=r"(r3) : "r"(a));
}
__device__ __forceinline__ void mma16816(float* c,
                                         uint32_t a0, uint32_t a1, uint32_t a2, uint32_t a3,
                                         uint32_t b0, uint32_t b1) {
    asm volatile("mma.sync.aligned.m16n8k16.row.col.f32.f16.f16.f32 "
                 "{%0,%1,%2,%3}, {%4,%5,%6,%7}, {%8,%9}, {%0,%1,%2,%3};\n"
                 : "+f"(c[0]), "+f"(c[1]), "+f"(c[2]), "+f"(c[3])
                 : "r"(a0), "r"(a1), "r"(a2), "r"(a3), "r"(b0), "r"(b1));
}

// ---------------- A-chunk staging: 64 rows x 128 halves, swizzled ----------------
__device__ __forceinline__ void stage_chunk(uint32_t abuf, const __half* g, int gstride) {
    int tid = threadIdx.x;
#pragma unroll
    for (int i = 0; i < 4; i++) {
        int idx = tid + i * 256;
        int r = idx >> 4;
        int kc = idx & 15;
        cp16(abuf + r * 256 + ((kc ^ (r & 7)) << 4), g + r * gstride + kc * 8);
    }
}

// ---------------- one GEMM accumulation phase: acc += A[64,K] @ Wslice(kb0..)^T ----------------
template<int KCHUNKS>
__device__ __forceinline__ void gemm_phase(float* acc, const __half* g, int gstride,
                                           uint32_t asmb, uint32_t wsmb, int wrowb, int kb0) {
    int tid  = threadIdx.x;
    int lane = tid & 31;
    int w    = tid >> 5;
    int m0 = (w & 3) * 16;
    int n0 = (w >> 2) * 8;
    int rA = m0 + (lane & 15);
    uint32_t abase = asmb + rA * 256;
    int asw = rA & 7;
    int akc = lane >> 4;
    int rB = n0 + (lane & 7);
    uint32_t bbase = wsmb + rB * wrowb;
    int bsw = rB & 7;
    int bm = lane >> 3;

    stage_chunk(asmb, g, gstride);
    cp_commit();
#pragma unroll
    for (int c = 0; c < KCHUNKS; c++) {
        if (c + 1 < KCHUNKS) {
            stage_chunk(asmb + ((c + 1) & 1) * 16384, g + (c + 1) * 128, gstride);
            cp_commit();
            cp_wait<1>();
        } else {
            cp_wait<0>();
        }
        __syncthreads();
        uint32_t ab = abase + (c & 1) * 16384;
        int kcc = (kb0 >> 3) + c * 16 + bm;
#pragma unroll
        for (int j = 0; j < 8; j += 2) {
            uint32_t b0, b1, b2, b3, a0, a1, a2, a3;
            ldsm4(b0, b1, b2, b3, bbase + (((kcc + 2 * j) ^ bsw) << 4));
            ldsm4(a0, a1, a2, a3, ab + (((2 * j + akc) ^ asw) << 4));
            mma16816(acc, a0, a1, a2, a3, b0, b1);
            ldsm4(a0, a1, a2, a3, ab + (((2 * j + 2 + akc) ^ asw) << 4));
            mma16816(acc, a0, a1, a2, a3, b2, b3);
        }
        __syncthreads();
    }
}

// ---------------- prep kernels ----------------
__global__ void prep_x_k(const float* __restrict__ x) {
    int i = blockIdx.x * 256 + threadIdx.x;   // one float2 each; B*T*F/2 = 4194304
    int f2 = i & 127;
    int t  = (i >> 7) & 511;
    int b  = i >> 16;
    float2 v = *(const float2*)(x + ((b * 512 + t) * 256 + f2 * 2));
    *((__half2*)(g_xh + (t * 64 + b) * 256 + f2 * 2)) = __floats2half2_rn(v.x, v.y);
}

__global__ void zero_k() {
    int i = blockIdx.x * 256 + threadIdx.x;   // 16384 threads -> B*H halves per buffer
    __half2 z = __floats2half2_rn(0.f, 0.f);
    ((__half2*)g_h0)[i] = z;
    ((__half2*)g_h1)[i] = z;
}

// ---------------- persistent recurrent layer kernel ----------------
template<int LAYER>
__global__ void __launch_bounds__(256, 1) lstm_k(
    const float* __restrict__ Wih, const float* __restrict__ Whh,
    const float* __restrict__ bih, const float* __restrict__ bhh,
    float* __restrict__ outp) {
    constexpr int KIN  = (LAYER == 0) ? 256 : 512;
    constexpr int KTOT = KIN + 512;
    constexpr int ROWB = KTOT * 2;                 // W smem row bytes
    constexpr int ASM_OFF = 16 * KTOT * 2;         // after W slice
    constexpr int GSM_OFF = ASM_OFF + 32768;       // after 2x16KB A buffers

    const __half* xin = (LAYER == 0) ? g_xh : (g_h0 + BB * HH);
    __half* hbuf      = (LAYER == 0) ? g_h0 : g_h1;

    extern __shared__ char dsm[];
    uint32_t smb  = (uint32_t)__cvta_generic_to_shared(dsm);
    uint32_t wsmb = smb;
    uint32_t asmb = smb + ASM_OFF;
    float* gsm = (float*)(dsm + GSM_OFF);          // [64][16] gate stash

    int tid = threadIdx.x;
    int bx  = blockIdx.x;

    // ---- load & convert this CTA's 16 W rows ([Wih | Whh] along k), swizzled fp16 ----
    for (int idx = tid; idx < 16 * KTOT / 4; idx += 256) {
        int n  = idx / (KTOT / 4);
        int kk = (idx % (KTOT / 4)) * 4;
        int gr = (n >> 2) * HH + bx * 4 + (n & 3);
        float4 v = (kk < KIN) ? *(const float4*)(Wih + gr * KIN + kk)
                              : *(const float4*)(Whh + gr * 512 + (kk - KIN));
        __half2 p0 = __floats2half2_rn(v.x, v.y);
        __half2 p1 = __floats2half2_rn(v.z, v.w);
        char* dst = dsm + n * ROWB + (((kk >> 3) ^ (n & 7)) << 4) + (kk & 7) * 2;
        *(__half2*)dst       = p0;
        *(__half2*)(dst + 4) = p1;
    }

    // ---- per-thread combined bias for this warp's two C columns ----
    int lane = tid & 31;
    int w    = tid >> 5;
    int m0 = (w & 3) * 16;
    int n0 = (w >> 2) * 8;
    int col0 = n0 + 2 * (lane & 3);
    int col1 = col0 + 1;
    float bias0 = bih[(col0 >> 2) * HH + bx * 4 + (col0 & 3)]
                + bhh[(col0 >> 2) * HH + bx * 4 + (col0 & 3)];
    float bias1 = bih[(col1 >> 2) * HH + bx * 4 + (col1 & 3)]
                + bhh[(col1 >> 2) * HH + bx * 4 + (col1 & 3)];
    __syncthreads();

    float cst = 0.f;                               // c-state for (b=tid>>2, u=tid&3)
    float acc[4] = {bias0, bias1, bias0, bias1};
    // prologue: x-contribution for step 1
    gemm_phase<KIN / 128>(acc, xin, KIN, asmb, wsmb, ROWB, 0);

    for (int t = 1; t <= TSTEPS; t++) {
        // h-contribution (critical path), K = 512
        gemm_phase<4>(acc, hbuf + (t - 1) * BB * HH, HH, asmb, wsmb, ROWB, KIN);

        // stash gates to smem
        int gid = lane >> 2, tig = lane & 3;
        float* s0 = gsm + (m0 + gid) * 16 + n0 + 2 * tig;
        s0[0] = acc[0]; s0[1] = acc[1];
        float* s1 = gsm + (m0 + 8 + gid) * 16 + n0 + 2 * tig;
        s1[0] = acc[2]; s1[1] = acc[3];
        __syncthreads();

        // pointwise LSTM cell: thread owns (b, u)
        int bb = tid >> 2, uu = tid & 3;
        float zi = gsm[bb * 16 + uu];
        float zf = gsm[bb * 16 + 4 + uu];
        float zg = gsm[bb * 16 + 8 + uu];
        float zo = gsm[bb * 16 + 12 + uu];
        float ival = 1.f / (1.f + __expf(-zi));
        float fval = 1.f / (1.f + __expf(-zf));
        float gval = tanhf(zg);
        float oval = 1.f / (1.f + __expf(-zo));
        cst = fval * cst + ival * gval;
        float hv = oval * tanhf(cst);
        hbuf[t * BB * HH + bb * HH + bx * 4 + uu] = __float2half(hv);
        if (LAYER == 1) outp[(bb * TSTEPS + (t - 1)) * HH + bx * 4 + uu] = hv;
        __syncthreads();

        if (t < TSTEPS) {
            // arrive at grid barrier, compute next step's x-contribution, then wait
            unsigned my = 0;
            if (tid == 0) {
                my = *(volatile unsigned*)&g_gen;
                __threadfence();
                if (atomicAdd(&g_cnt, 1u) == NCTA - 1) {
                    atomicExch(&g_cnt, 0u);
                    __threadfence();
                    *(volatile unsigned*)&g_gen = my + 1;
                }
            }
            acc[0] = bias0; acc[1] = bias1; acc[2] = bias0; acc[3] = bias1;
            gemm_phase<KIN / 128>(acc, xin + t * BB * KIN, KIN, asmb, wsmb, ROWB, 0);
            if (tid == 0) {
                while (*(volatile unsigned*)&g_gen == my) { }
                __threadfence();
            }
            __syncthreads();
        }
    }
}

// ---------------- host launcher ----------------
extern "C" void kernel_launch(void* const* d_in, const int* in_sizes, int n_in,
                              void* d_out, int out_size) {
    const float* x    = (const float*)d_in[0];
    const float* Wih0 = (const float*)d_in[1];
    const float* Whh0 = (const float*)d_in[2];
    const float* bih0 = (const float*)d_in[3];
    const float* bhh0 = (const float*)d_in[4];
    const float* Wih1 = (const float*)d_in[5];
    const float* Whh1 = (const float*)d_in[6];
    const float* bih1 = (const float*)d_in[7];
    const float* bhh1 = (const float*)d_in[8];
    float* out = (float*)d_out;

    cudaFuncSetAttribute(lstm_k<0>, cudaFuncAttributeMaxDynamicSharedMemorySize, 61440);
    cudaFuncSetAttribute(lstm_k<1>, cudaFuncAttributeMaxDynamicSharedMemorySize, 69632);

    prep_x_k<<<16384, 256>>>(x);
    zero_k<<<64, 256>>>();
    lstm_k<0><<<NCTA, 256, 61440>>>(Wih0, Whh0, bih0, bhh0, nullptr);
    lstm_k<1><<<NCTA, 256, 69632>>>(Wih1, Whh1, bih1, bhh1, out);
}

// round 4
// speedup vs baseline: 2.0001x; 2.0001x over previous
#include <cuda_runtime.h>
#include <cuda_fp16.h>
#include <cstdint>

#define BB 64
#define TSTEPS 512
#define HH 512

// ---------------- static device scratch ----------------
__device__ __align__(16) __half g_xh[TSTEPS * BB * 256];        // x fp16, [T][B][256]
__device__ __align__(16) __half g_h0[(TSTEPS + 1) * BB * HH];   // layer0 h seq, slot0 = 0
__device__ __align__(16) __half g_h1[(TSTEPS + 1) * BB * HH];   // layer1 h seq, slot0 = 0
__device__ unsigned g_c0;                                       // monotonic arrival counters
__device__ unsigned g_c1;

// ---------------- PTX helpers ----------------
__device__ __forceinline__ void cp16(uint32_t dst, const void* src) {
    asm volatile("cp.async.cg.shared.global [%0], [%1], 16;\n" :: "r"(dst), "l"(src));
}
__device__ __forceinline__ void cp_commit() { asm volatile("cp.async.commit_group;\n"); }
template<int N> __device__ __forceinline__ void cp_wait() {
    asm volatile("cp.async.wait_group %0;\n" :: "n"(N));
}
__device__ __forceinline__ void ldsm4(uint32_t& r0, uint32_t& r1, uint32_t& r2, uint32_t& r3,
                                      uint32_t a) {
    asm volatile("ldmatrix.sync.aligned.m8n8.x4.shared.b16 {%0,%1,%2,%3}, [%4];\n"
                 : "=r"(r0), "=r"(r1), "=r"(r2), "=r"(r3) : "r"(a));
}
__device__ __forceinline__ void mma16816(float* c,
                                         uint32_t a0, uint32_t a1, uint32_t a2, uint32_t a3,
                                         uint32_t b0, uint32_t b1) {
    asm volatile("mma.sync.aligned.m16n8k16.row.col.f32.f16.f16.f32 "
                 "{%0,%1,%2,%3}, {%4,%5,%6,%7}, {%8,%9}, {%0,%1,%2,%3};\n"
                 : "+f"(c[0]), "+f"(c[1]), "+f"(c[2]), "+f"(c[3])
                 : "r"(a0), "r"(a1), "r"(a2), "r"(a3), "r"(b0), "r"(b1));
}
__device__ __forceinline__ unsigned ld_acq(const unsigned* p) {
    unsigned v;
    asm volatile("ld.acquire.gpu.global.u32 %0, [%1];" : "=r"(v) : "l"(p) : "memory");
    return v;
}
__device__ __forceinline__ void red_rel(unsigned* p) {
    asm volatile("red.release.gpu.global.add.u32 [%0], 1;" :: "l"(p) : "memory");
}

// ---------------- A staging: 64 rows x UNITS 16B-units, swizzled ----------------
template<int UNITS>
__device__ __forceinline__ void stage(uint32_t dst, int arb, const __half* src,
                                      int sstride, int kcoff) {
    int tid = threadIdx.x;
#pragma unroll
    for (int i = 0; i < (64 * UNITS) / 256; i++) {
        int idx = tid + i * 256;
        int r = idx / UNITS, kc = idx % UNITS;
        cp16(dst + r * arb + (((kc + kcoff) ^ (r & 7)) << 4), src + r * sstride + kc * 8);
    }
}

// ---------------- GEMM: acc[64x32 tile] += A[64, 32*NP halves] @ Wslice^T ----------------
template<int NP>   // NP = kstep-pairs (covers 32*NP k-halves)
__device__ __forceinline__ void gemm(float* acc, uint32_t asmb, int arb,
                                     uint32_t wsmb, int rowb, int au0, int wu0) {
    int tid = threadIdx.x, lane = tid & 31, w = tid >> 5;
    int m0 = (w & 3) * 16, n0 = (w >> 2) * 16;
    int rA = m0 + (lane & 15);
    uint32_t abase = asmb + rA * arb;
    int asw = rA & 7, akc = lane >> 4;
    int rB = n0 + (lane & 7), bm = lane >> 3, bsw = rB & 7;
    uint32_t bb0 = wsmb + rB * rowb, bb1 = bb0 + 8 * rowb;
#pragma unroll
    for (int p = 0; p < NP; p++) {
        int au = au0 + 4 * p, wu = wu0 + 4 * p;
        uint32_t b0, b1, b2, b3, c0, c1, c2, c3, a0, a1, a2, a3;
        ldsm4(b0, b1, b2, b3, bb0 + (((wu + bm) ^ bsw) << 4));
        ldsm4(c0, c1, c2, c3, bb1 + (((wu + bm) ^ bsw) << 4));
        ldsm4(a0, a1, a2, a3, abase + (((au + akc) ^ asw) << 4));
        mma16816(acc,     a0, a1, a2, a3, b0, b1);
        mma16816(acc + 4, a0, a1, a2, a3, c0, c1);
        ldsm4(a0, a1, a2, a3, abase + (((au + 2 + akc) ^ asw) << 4));
        mma16816(acc,     a0, a1, a2, a3, b2, b3);
        mma16816(acc + 4, a0, a1, a2, a3, c2, c3);
    }
}

// ---------------- prep kernels ----------------
__global__ void prep_x_k(const float* __restrict__ x) {
    int i = blockIdx.x * 256 + threadIdx.x;
    int f2 = i & 127;
    int t  = (i >> 7) & 511;
    int b  = i >> 16;
    float2 v = *(const float2*)(x + ((b * 512 + t) * 256 + f2 * 2));
    *((__half2*)(g_xh + (t * 64 + b) * 256 + f2 * 2)) = __floats2half2_rn(v.x, v.y);
}

__global__ void zero_k() {
    int i = blockIdx.x * 256 + threadIdx.x;
    __half2 z = __floats2half2_rn(0.f, 0.f);
    ((__half2*)g_h0)[i] = z;
    ((__half2*)g_h1)[i] = z;
    if (i == 0) { g_c0 = 0; g_c1 = 0; }
}

// ---------------- fused two-layer pipelined persistent kernel ----------------
// CTAs [0,64): layer 0 (group 0). CTAs [64,128): layer 1 (group 1), lagging 1 step.
template<int GRP>
__device__ __forceinline__ void run_group(char* dsm, int lx,
        const float* __restrict__ Wih, const float* __restrict__ Whh,
        const float* __restrict__ bih, const float* __restrict__ bhh,
        float* __restrict__ outp) {
    constexpr int KIN  = GRP ? 512 : 256;
    constexpr int KTOT = KIN + 512;
    constexpr int ROWB = KTOT * 2;           // W smem row bytes
    constexpr int AOFF = 65536;              // A tile region
    constexpr int XOFF = 131072;             // group0 x-stage region
    constexpr int GOFF = 196608;             // gate stash (stride 33 floats)

    uint32_t smb = (uint32_t)__cvta_generic_to_shared(dsm);
    float* gsm = (float*)(dsm + GOFF);
    int tid = threadIdx.x, lane = tid & 31, w = tid >> 5;
    int m0 = (w & 3) * 16, n0 = (w >> 2) * 16;

    // ---- load & convert this CTA's 32 W rows ([Wih | Whh] along k), swizzled fp16 ----
    for (int idx = tid; idx < 32 * (KTOT / 4); idx += 256) {
        int n  = idx / (KTOT / 4);
        int kk = (idx % (KTOT / 4)) * 4;
        int gr = (n >> 3) * HH + lx * 8 + (n & 7);
        float4 v = (kk < KIN) ? *(const float4*)(Wih + (size_t)gr * KIN + kk)
                              : *(const float4*)(Whh + (size_t)gr * HH + (kk - KIN));
        __half2 p0 = __floats2half2_rn(v.x, v.y);
        __half2 p1 = __floats2half2_rn(v.z, v.w);
        char* dst = dsm + n * ROWB + (((kk >> 3) ^ (n & 7)) << 4) + (kk & 7) * 2;
        *(__half2*)dst       = p0;
        *(__half2*)(dst + 4) = p1;
    }

    int c0l = n0 + 2 * (lane & 3);
    int br0 = ((c0l) >> 3) * HH + lx * 8 + (c0l & 7);
    int br1 = ((c0l + 1) >> 3) * HH + lx * 8 + ((c0l + 1) & 7);
    int br2 = ((c0l + 8) >> 3) * HH + lx * 8 + ((c0l + 8) & 7);
    int br3 = ((c0l + 9) >> 3) * HH + lx * 8 + ((c0l + 9) & 7);
    float bias[4] = { bih[br0] + bhh[br0], bih[br1] + bhh[br1],
                      bih[br2] + bhh[br2], bih[br3] + bhh[br3] };
    __syncthreads();

    float cst[2] = {0.f, 0.f};
    float acc[8] = {bias[0], bias[1], bias[0], bias[1], bias[2], bias[3], bias[2], bias[3]};
    __half* hbuf = GRP ? g_h1 : g_h0;

    if (GRP == 0) {   // prologue: x contribution for step 1
        stage<32>(smb + XOFF, 512, g_xh, 256, 0);
        cp_commit(); cp_wait<0>(); __syncthreads();
        gemm<8>(acc, smb + XOFF, 512, smb, ROWB, 0, 0);
    }

    for (int t = 1; t <= TSTEPS; t++) {
        if (GRP == 0) {
            if (tid == 0) { while (ld_acq(&g_c0) < 64u * (t - 1)) {} }
            __syncthreads();
            const __half* hs = g_h0 + (size_t)(t - 1) * BB * HH;
            stage<32>(smb + AOFF, 1024, hs, 512, 0);        cp_commit();
            stage<32>(smb + AOFF, 1024, hs + 256, 512, 32); cp_commit();
            cp_wait<1>(); __syncthreads();
            gemm<8>(acc, smb + AOFF, 1024, smb, ROWB, 0, 32);
            cp_wait<0>(); __syncthreads();
            gemm<8>(acc, smb + AOFF, 1024, smb, ROWB, 32, 64);
        } else {
            if (tid == 0) { while (ld_acq(&g_c1) < 64u * (t - 1)) {} }
            __syncthreads();
            const __half* h1s = g_h1 + (size_t)(t - 1) * BB * HH;   // own recurrent input
            stage<32>(smb + AOFF, 2048, h1s, 512, 64);       cp_commit();
            stage<32>(smb + AOFF, 2048, h1s + 256, 512, 96); cp_commit();
            if (tid == 0) { while (ld_acq(&g_c0) < 64u * t) {} }    // wait for layer0 h[t]
            __syncthreads();
            const __half* h0s = g_h0 + (size_t)t * BB * HH;
            stage<32>(smb + AOFF, 2048, h0s, 512, 0);        cp_commit();
            stage<32>(smb + AOFF, 2048, h0s + 256, 512, 32); cp_commit();
            cp_wait<2>(); __syncthreads();
            gemm<16>(acc, smb + AOFF, 2048, smb, ROWB, 64, 64);   // h1 (recurrent) part
            cp_wait<0>(); __syncthreads();
            gemm<16>(acc, smb + AOFF, 2048, smb, ROWB, 0, 0);     // h0 (input) part
        }

        // ---- stash gates (stride 33 to dodge bank conflicts) ----
        int r0 = m0 + (lane >> 2), r1 = r0 + 8;
        gsm[r0 * 33 + c0l]     = acc[0]; gsm[r0 * 33 + c0l + 1] = acc[1];
        gsm[r1 * 33 + c0l]     = acc[2]; gsm[r1 * 33 + c0l + 1] = acc[3];
        gsm[r0 * 33 + c0l + 8] = acc[4]; gsm[r0 * 33 + c0l + 9] = acc[5];
        gsm[r1 * 33 + c0l + 8] = acc[6]; gsm[r1 * 33 + c0l + 9] = acc[7];
        __syncthreads();

        // ---- pointwise LSTM cell: 2 (b,u) pairs per thread ----
#pragma unroll
        for (int q = 0; q < 2; q++) {
            int p = tid + q * 256, b = p >> 3, u = p & 7;
            int base = b * 33 + u;
            float zi = gsm[base], zf = gsm[base + 8], zg = gsm[base + 16], zo = gsm[base + 24];
            float iv = 1.f / (1.f + __expf(-zi));
            float fv = 1.f / (1.f + __expf(-zf));
            float gv = tanhf(zg);
            float ov = 1.f / (1.f + __expf(-zo));
            cst[q] = fv * cst[q] + iv * gv;
            float hv = ov * tanhf(cst[q]);
            hbuf[(size_t)t * BB * HH + b * HH + lx * 8 + u] = __float2half(hv);
            if (GRP == 1) outp[((size_t)b * TSTEPS + (t - 1)) * HH + lx * 8 + u] = hv;
        }
        __syncthreads();
        if (tid == 0) red_rel(GRP ? &g_c1 : &g_c0);   // release: h[t] published

        acc[0] = bias[0]; acc[1] = bias[1]; acc[2] = bias[0]; acc[3] = bias[1];
        acc[4] = bias[2]; acc[5] = bias[3]; acc[6] = bias[2]; acc[7] = bias[3];

        if (GRP == 0 && t < TSTEPS) {   // overlap barrier wait with x(t+1) GEMM
            stage<32>(smb + XOFF, 512, g_xh + (size_t)t * BB * 256, 256, 0);
            cp_commit(); cp_wait<0>(); __syncthreads();
            gemm<8>(acc, smb + XOFF, 512, smb, ROWB, 0, 0);
        }
    }
}

__global__ void __launch_bounds__(256, 1) lstm_fused(
        const float* __restrict__ Wih0, const float* __restrict__ Whh0,
        const float* __restrict__ bih0, const float* __restrict__ bhh0,
        const float* __restrict__ Wih1, const float* __restrict__ Whh1,
        const float* __restrict__ bih1, const float* __restrict__ bhh1,
        float* __restrict__ outp) {
    extern __shared__ char dsm[];
    int bx = blockIdx.x;
    if (bx < 64) run_group<0>(dsm, bx,      Wih0, Whh0, bih0, bhh0, nullptr);
    else         run_group<1>(dsm, bx - 64, Wih1, Whh1, bih1, bhh1, outp);
}

// ---------------- host launcher ----------------
extern "C" void kernel_launch(void* const* d_in, const int* in_sizes, int n_in,
                              void* d_out, int out_size) {
    const float* x    = (const float*)d_in[0];
    const float* Wih0 = (const float*)d_in[1];
    const float* Whh0 = (const float*)d_in[2];
    const float* bih0 = (const float*)d_in[3];
    const float* bhh0 = (const float*)d_in[4];
    const float* Wih1 = (const float*)d_in[5];
    const float* Whh1 = (const float*)d_in[6];
    const float* bih1 = (const float*)d_in[7];
    const float* bhh1 = (const float*)d_in[8];
    float* out = (float*)d_out;

    cudaFuncSetAttribute(lstm_fused, cudaFuncAttributeMaxDynamicSharedMemorySize, 205056);

    prep_x_k<<<16384, 256>>>(x);
    zero_k<<<64, 256>>>();
    lstm_fused<<<128, 256, 205056>>>(Wih0, Whh0, bih0, bhh0,
                                     Wih1, Whh1, bih1, bhh1, out);
}

// round 5
// speedup vs baseline: 2.0014x; 1.0007x over previous
#include <cuda_runtime.h>
#include <cuda_fp16.h>
#include <cstdint>

#define BB 64
#define TSTEPS 512
#define HH 512

// ---------------- static device scratch ----------------
__device__ __align__(16) __half g_xh[TSTEPS * BB * 256];        // x fp16, [T][B][256]
__device__ __align__(16) __half g_h0[(TSTEPS + 1) * BB * HH];   // layer0 h seq, slot0 = 0
__device__ __align__(16) __half g_h1[(TSTEPS + 1) * BB * HH];   // layer1 h seq, slot0 = 0
__device__ unsigned g_c0;                                       // monotonic arrival counters
__device__ unsigned g_c1;

// ---------------- PTX helpers ----------------
__device__ __forceinline__ void cp16(uint32_t dst, const void* src) {
    asm volatile("cp.async.cg.shared.global [%0], [%1], 16;\n" :: "r"(dst), "l"(src));
}
__device__ __forceinline__ void cp_commit() { asm volatile("cp.async.commit_group;\n"); }
template<int N> __device__ __forceinline__ void cp_wait() {
    asm volatile("cp.async.wait_group %0;\n" :: "n"(N));
}
__device__ __forceinline__ void ldsm4(uint32_t& r0, uint32_t& r1, uint32_t& r2, uint32_t& r3,
                                      uint32_t a) {
    asm volatile("ldmatrix.sync.aligned.m8n8.x4.shared.b16 {%0,%1,%2,%3}, [%4];\n"
                 : "=r"(r0), "=r"(r1), "=r"(r2), "=r"(r3) : "r"(a));
}
__device__ __forceinline__ void mma16816(float* c,
                                         uint32_t a0, uint32_t a1, uint32_t a2, uint32_t a3,
                                         uint32_t b0, uint32_t b1) {
    asm volatile("mma.sync.aligned.m16n8k16.row.col.f32.f16.f16.f32 "
                 "{%0,%1,%2,%3}, {%4,%5,%6,%7}, {%8,%9}, {%0,%1,%2,%3};\n"
                 : "+f"(c[0]), "+f"(c[1]), "+f"(c[2]), "+f"(c[3])
                 : "r"(a0), "r"(a1), "r"(a2), "r"(a3), "r"(b0), "r"(b1));
}
__device__ __forceinline__ unsigned ld_acq(const unsigned* p) {
    unsigned v;
    asm volatile("ld.acquire.gpu.global.u32 %0, [%1];" : "=r"(v) : "l"(p) : "memory");
    return v;
}
__device__ __forceinline__ void red_rel(unsigned* p) {
    asm volatile("red.release.gpu.global.add.u32 [%0], 1;" :: "l"(p) : "memory");
}

// ---------------- A staging: 64 rows x UNITS 16B-units, swizzled ----------------
template<int UNITS>
__device__ __forceinline__ void stage(uint32_t dst, int arb, const __half* src,
                                      int sstride, int kcoff) {
    int tid = threadIdx.x;
#pragma unroll
    for (int i = 0; i < (64 * UNITS) / 256; i++) {
        int idx = tid + i * 256;
        int r = idx / UNITS, kc = idx % UNITS;
        cp16(dst + r * arb + (((kc + kcoff) ^ (r & 7)) << 4), src + r * sstride + kc * 8);
    }
}

// ---------------- GEMM: acc[64x32 tile] += A[64, 32*NP halves] @ Wslice^T ----------------
template<int NP>   // NP = kstep-pairs (covers 32*NP k-halves)
__device__ __forceinline__ void gemm(float* acc, uint32_t asmb, int arb,
                                     uint32_t wsmb, int rowb, int au0, int wu0) {
    int tid = threadIdx.x, lane = tid & 31, w = tid >> 5;
    int m0 = (w & 3) * 16, n0 = (w >> 2) * 16;
    int rA = m0 + (lane & 15);
    uint32_t abase = asmb + rA * arb;
    int asw = rA & 7, akc = lane >> 4;
    int rB = n0 + (lane & 7), bm = lane >> 3, bsw = rB & 7;
    uint32_t bb0 = wsmb + rB * rowb, bb1 = bb0 + 8 * rowb;
#pragma unroll
    for (int p = 0; p < NP; p++) {
        int au = au0 + 4 * p, wu = wu0 + 4 * p;
        uint32_t b0, b1, b2, b3, c0, c1, c2, c3, a0, a1, a2, a3;
        ldsm4(b0, b1, b2, b3, bb0 + (((wu + bm) ^ bsw) << 4));
        ldsm4(c0, c1, c2, c3, bb1 + (((wu + bm) ^ bsw) << 4));
        ldsm4(a0, a1, a2, a3, abase + (((au + akc) ^ asw) << 4));
        mma16816(acc,     a0, a1, a2, a3, b0, b1);
        mma16816(acc + 4, a0, a1, a2, a3, c0, c1);
        ldsm4(a0, a1, a2, a3, abase + (((au + 2 + akc) ^ asw) << 4));
        mma16816(acc,     a0, a1, a2, a3, b2, b3);
        mma16816(acc + 4, a0, a1, a2, a3, c2, c3);
    }
}

// ---------------- prep kernels ----------------
__global__ void prep_x_k(const float* __restrict__ x) {
    int i = blockIdx.x * 256 + threadIdx.x;
    int f2 = i & 127;
    int t  = (i >> 7) & 511;
    int b  = i >> 16;
    float2 v = *(const float2*)(x + ((b * 512 + t) * 256 + f2 * 2));
    *((__half2*)(g_xh + (t * 64 + b) * 256 + f2 * 2)) = __floats2half2_rn(v.x, v.y);
}

__global__ void zero_k() {
    int i = blockIdx.x * 256 + threadIdx.x;
    __half2 z = __floats2half2_rn(0.f, 0.f);
    ((__half2*)g_h0)[i] = z;
    ((__half2*)g_h1)[i] = z;
    if (i == 0) { g_c0 = 0; g_c1 = 0; }
}

// ---------------- fused two-layer pipelined persistent kernel ----------------
// CTAs [0,64): layer 0 (group 0). CTAs [64,128): layer 1 (group 1), lagging 1 step.
template<int GRP>
__device__ __forceinline__ void run_group(char* dsm, int lx,
        const float* __restrict__ Wih, const float* __restrict__ Whh,
        const float* __restrict__ bih, const float* __restrict__ bhh,
        float* __restrict__ outp) {
    constexpr int KIN  = GRP ? 512 : 256;
    constexpr int KTOT = KIN + 512;
    constexpr int ROWB = KTOT * 2;           // W smem row bytes
    constexpr int AOFF = 65536;              // A tile region
    constexpr int XOFF = 131072;             // group0 x-stage region
    constexpr int GOFF = 196608;             // gate stash (stride 33 floats)

    uint32_t smb = (uint32_t)__cvta_generic_to_shared(dsm);
    float* gsm = (float*)(dsm + GOFF);
    int tid = threadIdx.x, lane = tid & 31, w = tid >> 5;
    int m0 = (w & 3) * 16, n0 = (w >> 2) * 16;

    // ---- load & convert this CTA's 32 W rows ([Wih | Whh] along k), swizzled fp16 ----
    for (int idx = tid; idx < 32 * (KTOT / 4); idx += 256) {
        int n  = idx / (KTOT / 4);
        int kk = (idx % (KTOT / 4)) * 4;
        int gr = (n >> 3) * HH + lx * 8 + (n & 7);
        float4 v = (kk < KIN) ? *(const float4*)(Wih + (size_t)gr * KIN + kk)
                              : *(const float4*)(Whh + (size_t)gr * HH + (kk - KIN));
        __half2 p0 = __floats2half2_rn(v.x, v.y);
        __half2 p1 = __floats2half2_rn(v.z, v.w);
        char* dst = dsm + n * ROWB + (((kk >> 3) ^ (n & 7)) << 4) + (kk & 7) * 2;
        *(__half2*)dst       = p0;
        *(__half2*)(dst + 4) = p1;
    }

    int c0l = n0 + 2 * (lane & 3);
    int br0 = ((c0l) >> 3) * HH + lx * 8 + (c0l & 7);
    int br1 = ((c0l + 1) >> 3) * HH + lx * 8 + ((c0l + 1) & 7);
    int br2 = ((c0l + 8) >> 3) * HH + lx * 8 + ((c0l + 8) & 7);
    int br3 = ((c0l + 9) >> 3) * HH + lx * 8 + ((c0l + 9) & 7);
    float bias[4] = { bih[br0] + bhh[br0], bih[br1] + bhh[br1],
                      bih[br2] + bhh[br2], bih[br3] + bhh[br3] };
    __syncthreads();

    float cst[2] = {0.f, 0.f};
    float acc[8] = {bias[0], bias[1], bias[0], bias[1], bias[2], bias[3], bias[2], bias[3]};
    __half* hbuf = GRP ? g_h1 : g_h0;

    if (GRP == 0) {   // prologue: x contribution for step 1
        stage<32>(smb + XOFF, 512, g_xh, 256, 0);
        cp_commit(); cp_wait<0>(); __syncthreads();
        gemm<8>(acc, smb + XOFF, 512, smb, ROWB, 0, 0);
    }

    for (int t = 1; t <= TSTEPS; t++) {
        if (GRP == 0) {
            if (tid == 0) { while (ld_acq(&g_c0) < 64u * (t - 1)) {} }
            __syncthreads();
            const __half* hs = g_h0 + (size_t)(t - 1) * BB * HH;
            stage<32>(smb + AOFF, 1024, hs, 512, 0);        cp_commit();
            stage<32>(smb + AOFF, 1024, hs + 256, 512, 32); cp_commit();
            cp_wait<1>(); __syncthreads();
            gemm<8>(acc, smb + AOFF, 1024, smb, ROWB, 0, 32);
            cp_wait<0>(); __syncthreads();
            gemm<8>(acc, smb + AOFF, 1024, smb, ROWB, 32, 64);
        } else {
            if (tid == 0) { while (ld_acq(&g_c1) < 64u * (t - 1)) {} }
            __syncthreads();
            const __half* h1s = g_h1 + (size_t)(t - 1) * BB * HH;   // own recurrent input
            stage<32>(smb + AOFF, 2048, h1s, 512, 64);       cp_commit();
            stage<32>(smb + AOFF, 2048, h1s + 256, 512, 96); cp_commit();
            if (tid == 0) { while (ld_acq(&g_c0) < 64u * t) {} }    // wait for layer0 h[t]
            __syncthreads();
            const __half* h0s = g_h0 + (size_t)t * BB * HH;
            stage<32>(smb + AOFF, 2048, h0s, 512, 0);        cp_commit();
            stage<32>(smb + AOFF, 2048, h0s + 256, 512, 32); cp_commit();
            cp_wait<2>(); __syncthreads();
            gemm<16>(acc, smb + AOFF, 2048, smb, ROWB, 64, 64);   // h1 (recurrent) part
            cp_wait<0>(); __syncthreads();
            gemm<16>(acc, smb + AOFF, 2048, smb, ROWB, 0, 0);     // h0 (input) part
        }

        // ---- stash gates (stride 33 to dodge bank conflicts) ----
        int r0 = m0 + (lane >> 2), r1 = r0 + 8;
        gsm[r0 * 33 + c0l]     = acc[0]; gsm[r0 * 33 + c0l + 1] = acc[1];
        gsm[r1 * 33 + c0l]     = acc[2]; gsm[r1 * 33 + c0l + 1] = acc[3];
        gsm[r0 * 33 + c0l + 8] = acc[4]; gsm[r0 * 33 + c0l + 9] = acc[5];
        gsm[r1 * 33 + c0l + 8] = acc[6]; gsm[r1 * 33 + c0l + 9] = acc[7];
        __syncthreads();

        // ---- pointwise LSTM cell: 2 (b,u) pairs per thread ----
#pragma unroll
        for (int q = 0; q < 2; q++) {
            int p = tid + q * 256, b = p >> 3, u = p & 7;
            int base = b * 33 + u;
            float zi = gsm[base], zf = gsm[base + 8], zg = gsm[base + 16], zo = gsm[base + 24];
            float iv = 1.f / (1.f + __expf(-zi));
            float fv = 1.f / (1.f + __expf(-zf));
            float gv = tanhf(zg);
            float ov = 1.f / (1.f + __expf(-zo));
            cst[q] = fv * cst[q] + iv * gv;
            float hv = ov * tanhf(cst[q]);
            hbuf[(size_t)t * BB * HH + b * HH + lx * 8 + u] = __float2half(hv);
            if (GRP == 1) outp[((size_t)b * TSTEPS + (t - 1)) * HH + lx * 8 + u] = hv;
        }
        __syncthreads();
        if (tid == 0) red_rel(GRP ? &g_c1 : &g_c0);   // release: h[t] published

        acc[0] = bias[0]; acc[1] = bias[1]; acc[2] = bias[0]; acc[3] = bias[1];
        acc[4] = bias[2]; acc[5] = bias[3]; acc[6] = bias[2]; acc[7] = bias[3];

        if (GRP == 0 && t < TSTEPS) {   // overlap barrier wait with x(t+1) GEMM
            stage<32>(smb + XOFF, 512, g_xh + (size_t)t * BB * 256, 256, 0);
            cp_commit(); cp_wait<0>(); __syncthreads();
            gemm<8>(acc, smb + XOFF, 512, smb, ROWB, 0, 0);
        }
    }
}

__global__ void __launch_bounds__(256, 1) lstm_fused(
        const float* __restrict__ Wih0, const float* __restrict__ Whh0,
        const float* __restrict__ bih0, const float* __restrict__ bhh0,
        const float* __restrict__ Wih1, const float* __restrict__ Whh1,
        const float* __restrict__ bih1, const float* __restrict__ bhh1,
        float* __restrict__ outp) {
    extern __shared__ char dsm[];
    int bx = blockIdx.x;
    if (bx < 64) run_group<0>(dsm, bx,      Wih0, Whh0, bih0, bhh0, nullptr);
    else         run_group<1>(dsm, bx - 64, Wih1, Whh1, bih1, bhh1, outp);
}

// ---------------- host launcher ----------------
extern "C" void kernel_launch(void* const* d_in, const int* in_sizes, int n_in,
                              void* d_out, int out_size) {
    const float* x    = (const float*)d_in[0];
    const float* Wih0 = (const float*)d_in[1];
    const float* Whh0 = (const float*)d_in[2];
    const float* bih0 = (const float*)d_in[3];
    const float* bhh0 = (const float*)d_in[4];
    const float* Wih1 = (const float*)d_in[5];
    const float* Whh1 = (const float*)d_in[6];
    const float* bih1 = (const float*)d_in[7];
    const float* bhh1 = (const float*)d_in[8];
    float* out = (float*)d_out;

    cudaFuncSetAttribute(lstm_fused, cudaFuncAttributeMaxDynamicSharedMemorySize, 205056);

    prep_x_k<<<16384, 256>>>(x);
    zero_k<<<64, 256>>>();
    lstm_fused<<<128, 256, 205056>>>(Wih0, Whh0, bih0, bhh0,
                                     Wih1, Whh1, bih1, bhh1, out);
}

// round 6
// speedup vs baseline: 2.2244x; 1.1114x over previous
#include <cuda_runtime.h>
#include <cuda_fp16.h>
#include <cstdint>

#define BB 64
#define TSTEPS 512
#define HH 512

// ---------------- static device scratch ----------------
__device__ __align__(16) __half g_xh[TSTEPS * BB * 256];        // x fp16, [T][B][256]
__device__ __align__(16) __half g_h0[(TSTEPS + 1) * BB * HH];   // layer0 h seq, slot0 = 0
__device__ __align__(16) __half g_h1[(TSTEPS + 1) * BB * HH];   // layer1 h seq, slot0 = 0
__device__ unsigned g_c0;                                       // monotonic arrival counters
__device__ unsigned g_c1;

// ---------------- PTX helpers ----------------
__device__ __forceinline__ void cp16(uint32_t dst, const void* src) {
    asm volatile("cp.async.cg.shared.global [%0], [%1], 16;\n" :: "r"(dst), "l"(src));
}
__device__ __forceinline__ void cp_commit() { asm volatile("cp.async.commit_group;\n"); }
template<int N> __device__ __forceinline__ void cp_wait() {
    asm volatile("cp.async.wait_group %0;\n" :: "n"(N));
}
__device__ __forceinline__ void ldsm4(uint32_t& r0, uint32_t& r1, uint32_t& r2, uint32_t& r3,
                                      uint32_t a) {
    asm volatile("ldmatrix.sync.aligned.m8n8.x4.shared.b16 {%0,%1,%2,%3}, [%4];\n"
                 : "=r"(r0), "=r"(r1), "=r"(r2), "=r"(r3) : "r"(a));
}
__device__ __forceinline__ void mma16816(float* c,
                                         uint32_t a0, uint32_t a1, uint32_t a2, uint32_t a3,
                                         uint32_t b0, uint32_t b1) {
    asm volatile("mma.sync.aligned.m16n8k16.row.col.f32.f16.f16.f32 "
                 "{%0,%1,%2,%3}, {%4,%5,%6,%7}, {%8,%9}, {%0,%1,%2,%3};\n"
                 : "+f"(c[0]), "+f"(c[1]), "+f"(c[2]), "+f"(c[3])
                 : "r"(a0), "r"(a1), "r"(a2), "r"(a3), "r"(b0), "r"(b1));
}
__device__ __forceinline__ unsigned ld_acq(const unsigned* p) {
    unsigned v;
    asm volatile("ld.acquire.gpu.global.u32 %0, [%1];" : "=r"(v) : "l"(p) : "memory");
    return v;
}
__device__ __forceinline__ void red_rel(unsigned* p) {
    asm volatile("red.release.gpu.global.add.u32 [%0], 1;" :: "l"(p) : "memory");
}

// ---------------- A staging: 64 rows x UNITS 16B-units, swizzled (512 thr) ----------------
template<int UNITS>
__device__ __forceinline__ void stage(uint32_t dst, int arb, const __half* src,
                                      int sstride, int kcoff) {
    int tid = threadIdx.x;
#pragma unroll
    for (int i = 0; i < (64 * UNITS) / 512; i++) {
        int idx = tid + i * 512;
        int r = idx / UNITS, kc = idx % UNITS;
        cp16(dst + r * arb + (((kc + kcoff) ^ (r & 7)) << 4), src + r * sstride + kc * 8);
    }
}

// ---------------- GEMM: per-warp 16x16 C tile over NP*4 16B-units of K ----------------
// au0/wu0 are 16B-unit indices and already include the warp's k-split offset.
template<int NP>
__device__ __forceinline__ void gemm(float* acc, uint32_t asmb, int arb,
                                     uint32_t wsmb, int rowb, int au0, int wu0) {
    int tid = threadIdx.x, lane = tid & 31, w = tid >> 5;
    int m0 = (w & 3) * 16, n0 = ((w >> 2) & 1) * 16;
    int rA = m0 + (lane & 15);
    uint32_t abase = asmb + rA * arb;
    int asw = rA & 7, akc = lane >> 4;
    int rB = n0 + (lane & 7), bm = lane >> 3, bsw = rB & 7;
    uint32_t bb0 = wsmb + rB * rowb, bb1 = bb0 + 8 * rowb;
#pragma unroll
    for (int p = 0; p < NP; p++) {
        int au = au0 + 4 * p, wu = wu0 + 4 * p;
        uint32_t b0, b1, b2, b3, c0, c1, c2, c3, a0, a1, a2, a3;
        ldsm4(b0, b1, b2, b3, bb0 + (((wu + bm) ^ bsw) << 4));
        ldsm4(c0, c1, c2, c3, bb1 + (((wu + bm) ^ bsw) << 4));
        ldsm4(a0, a1, a2, a3, abase + (((au + akc) ^ asw) << 4));
        mma16816(acc,     a0, a1, a2, a3, b0, b1);
        mma16816(acc + 4, a0, a1, a2, a3, c0, c1);
        ldsm4(a0, a1, a2, a3, abase + (((au + 2 + akc) ^ asw) << 4));
        mma16816(acc,     a0, a1, a2, a3, b2, b3);
        mma16816(acc + 4, a0, a1, a2, a3, c2, c3);
    }
}

// ---------------- prep kernels ----------------
__global__ void prep_x_k(const float* __restrict__ x) {
    int i = blockIdx.x * 256 + threadIdx.x;
    int f2 = i & 127;
    int t  = (i >> 7) & 511;
    int b  = i >> 16;
    float2 v = *(const float2*)(x + ((b * 512 + t) * 256 + f2 * 2));
    *((__half2*)(g_xh + (t * 64 + b) * 256 + f2 * 2)) = __floats2half2_rn(v.x, v.y);
}

__global__ void zero_k() {
    int i = blockIdx.x * 256 + threadIdx.x;
    __half2 z = __floats2half2_rn(0.f, 0.f);
    ((__half2*)g_h0)[i] = z;
    ((__half2*)g_h1)[i] = z;
    if (i == 0) { g_c0 = 0; g_c1 = 0; }
}

// ---------------- fused two-layer pipelined persistent kernel ----------------
// CTAs [0,64): layer 0. CTAs [64,128): layer 1 (pipelined one step behind).
// 512 threads: 16 warps = 4(m) x 2(n) x 2(k-split).
template<int GRP>
__device__ __forceinline__ void run_group(char* dsm, int lx,
        const float* __restrict__ Wih, const float* __restrict__ Whh,
        const float* __restrict__ bih, const float* __restrict__ bhh,
        float* __restrict__ outp) {
    constexpr int KIN  = GRP ? 512 : 256;
    constexpr int KTOT = KIN + 512;
    constexpr int ROWB = KTOT * 2;           // W smem row bytes
    constexpr int AOFF = 65536;              // h staging region
    constexpr int ARB  = GRP ? 2048 : 1024;  // A row bytes
    constexpr int XOFF = 131072;             // group0 x staging region
    constexpr int GOFF = 196608;             // gate stashes

    uint32_t smb = (uint32_t)__cvta_generic_to_shared(dsm);
    float* gsm0 = (float*)(dsm + GOFF);      // k-half 0 stash, stride 40
    float* gsm1 = gsm0 + 2560;               // k-half 1 stash
    float* bsm  = gsm1 + 2560;               // 32 combined biases

    int tid = threadIdx.x, lane = tid & 31, w = tid >> 5;
    int m0 = (w & 3) * 16, n0 = ((w >> 2) & 1) * 16, kq = w >> 3;

    // ---- load & convert this CTA's 32 W rows ([Wih | Whh] along k), swizzled fp16 ----
    for (int idx = tid; idx < 32 * (KTOT / 4); idx += 512) {
        int n  = idx / (KTOT / 4);
        int kk = (idx % (KTOT / 4)) * 4;
        int gr = (n >> 3) * HH + lx * 8 + (n & 7);
        float4 v = (kk < KIN) ? *(const float4*)(Wih + (size_t)gr * KIN + kk)
                              : *(const float4*)(Whh + (size_t)gr * HH + (kk - KIN));
        __half2 p0 = __floats2half2_rn(v.x, v.y);
        __half2 p1 = __floats2half2_rn(v.z, v.w);
        char* dst = dsm + n * ROWB + (((kk >> 3) ^ (n & 7)) << 4) + (kk & 7) * 2;
        *(__half2*)dst       = p0;
        *(__half2*)(dst + 4) = p1;
    }
    if (tid < 32) {
        int gr = (tid >> 3) * HH + lx * 8 + (tid & 7);
        bsm[tid] = bih[gr] + bhh[gr];
    }
    __syncthreads();

    float cst = 0.f;
    float acc[8] = {0.f, 0.f, 0.f, 0.f, 0.f, 0.f, 0.f, 0.f};
    __half* hbuf = GRP ? g_h1 : g_h0;

    if (GRP == 0) {   // prologue: x contribution for step 1
        stage<32>(smb + XOFF, 512, g_xh, 256, 0);
        cp_commit(); cp_wait<0>(); __syncthreads();
        gemm<4>(acc, smb + XOFF, 512, smb, ROWB, kq * 16, kq * 16);
    }

    for (int t = 1; t <= TSTEPS; t++) {
        if (GRP == 0) {
            if (tid == 0) { while (ld_acq(&g_c0) < 64u * (t - 1)) {} }
            __syncthreads();
            stage<64>(smb + AOFF, ARB, g_h0 + (size_t)(t - 1) * BB * HH, 512, 0);
            cp_commit(); cp_wait<0>(); __syncthreads();
            gemm<8>(acc, smb + AOFF, ARB, smb, ROWB, kq * 32, 32 + kq * 32);
        } else {
            // h0[t] input part first: group0 runs ahead, so this executes in the
            // shadow of our own group's h1[t-1] publication.
            if (tid == 0) { while (ld_acq(&g_c0) < 64u * t) {} }
            __syncthreads();
            stage<64>(smb + AOFF, ARB, g_h0 + (size_t)t * BB * HH, 512, 0);
            cp_commit();
            if (tid == 0) { while (ld_acq(&g_c1) < 64u * (t - 1)) {} }
            __syncthreads();
            stage<64>(smb + AOFF, ARB, g_h1 + (size_t)(t - 1) * BB * HH, 512, 64);
            cp_commit();
            cp_wait<1>(); __syncthreads();
            gemm<8>(acc, smb + AOFF, ARB, smb, ROWB, kq * 32, kq * 32);       // h0 part
            cp_wait<0>(); __syncthreads();
            gemm<8>(acc, smb + AOFF, ARB, smb, ROWB, 64 + kq * 32, 64 + kq * 32); // h1 part
        }

        // ---- stash gates (k-halves to separate regions, stride 40) ----
        {
            float* gs = kq ? gsm1 : gsm0;
            int c0l = n0 + 2 * (lane & 3);
            int r0 = m0 + (lane >> 2), r1 = r0 + 8;
            gs[r0 * 40 + c0l]     = acc[0]; gs[r0 * 40 + c0l + 1] = acc[1];
            gs[r1 * 40 + c0l]     = acc[2]; gs[r1 * 40 + c0l + 1] = acc[3];
            gs[r0 * 40 + c0l + 8] = acc[4]; gs[r0 * 40 + c0l + 9] = acc[5];
            gs[r1 * 40 + c0l + 8] = acc[6]; gs[r1 * 40 + c0l + 9] = acc[7];
        }
        __syncthreads();

        // ---- pointwise LSTM cell: thread owns one (b, u) ----
        {
            int b = tid >> 3, u = tid & 7, base = b * 40 + u;
            float zi = gsm0[base]      + gsm1[base]      + bsm[u];
            float zf = gsm0[base + 8]  + gsm1[base + 8]  + bsm[u + 8];
            float zg = gsm0[base + 16] + gsm1[base + 16] + bsm[u + 16];
            float zo = gsm0[base + 24] + gsm1[base + 24] + bsm[u + 24];
            float iv = 1.f / (1.f + __expf(-zi));
            float fv = 1.f / (1.f + __expf(-zf));
            float gv = tanhf(zg);
            float ov = 1.f / (1.f + __expf(-zo));
            cst = fv * cst + iv * gv;
            float hv = ov * tanhf(cst);
            hbuf[(size_t)t * BB * HH + b * HH + lx * 8 + u] = __float2half(hv);
            if (GRP == 1) outp[((size_t)b * TSTEPS + (t - 1)) * HH + lx * 8 + u] = hv;
        }
        __syncthreads();
        if (tid == 0) red_rel(GRP ? &g_c1 : &g_c0);   // release: h[t] published

#pragma unroll
        for (int i = 0; i < 8; i++) acc[i] = 0.f;

        if (GRP == 0 && t < TSTEPS) {   // x(t+1) GEMM in the publish shadow
            stage<32>(smb + XOFF, 512, g_xh + (size_t)t * BB * 256, 256, 0);
            cp_commit(); cp_wait<0>(); __syncthreads();
            gemm<4>(acc, smb + XOFF, 512, smb, ROWB, kq * 16, kq * 16);
        }
    }
}

__global__ void __launch_bounds__(512, 1) lstm_fused(
        const float* __restrict__ Wih0, const float* __restrict__ Whh0,
        const float* __restrict__ bih0, const float* __restrict__ bhh0,
        const float* __restrict__ Wih1, const float* __restrict__ Whh1,
        const float* __restrict__ bih1, const float* __restrict__ bhh1,
        float* __restrict__ outp) {
    extern __shared__ char dsm[];
    int bx = blockIdx.x;
    if (bx < 64) run_group<0>(dsm, bx,      Wih0, Whh0, bih0, bhh0, nullptr);
    else         run_group<1>(dsm, bx - 64, Wih1, Whh1, bih1, bhh1, outp);
}

// ---------------- host launcher ----------------
extern "C" void kernel_launch(void* const* d_in, const int* in_sizes, int n_in,
                              void* d_out, int out_size) {
    const float* x    = (const float*)d_in[0];
    const float* Wih0 = (const float*)d_in[1];
    const float* Whh0 = (const float*)d_in[2];
    const float* bih0 = (const float*)d_in[3];
    const float* bhh0 = (const float*)d_in[4];
    const float* Wih1 = (const float*)d_in[5];
    const float* Whh1 = (const float*)d_in[6];
    const float* bih1 = (const float*)d_in[7];
    const float* bhh1 = (const float*)d_in[8];
    float* out = (float*)d_out;

    cudaFuncSetAttribute(lstm_fused, cudaFuncAttributeMaxDynamicSharedMemorySize, 217216);

    prep_x_k<<<16384, 256>>>(x);
    zero_k<<<64, 256>>>();
    lstm_fused<<<128, 512, 217216>>>(Wih0, Whh0, bih0, bhh0,
                                     Wih1, Whh1, bih1, bhh1, out);
}